// round 5
// baseline (speedup 1.0000x reference)
#include <cuda_runtime.h>
#include <cstdint>
#include <cstddef>

#define L     1024
#define DM    256
#define DI    512
#define DS    16
#define RK    16
#define NSEQ  4
#define ROWS  (NSEQ*L)      // 4096
#define CH    8
#define CLEN  (L/CH)        // 128

// ---------------- device scratch (static globals: allocation-free) ----------------
__device__ float g_a0[ROWS*DM];          // activation ping
__device__ float g_a1[ROWS*DM];          // activation pong
__device__ float g_xz[ROWS*2*DI];        // in_proj output (xc | z)
__device__ float g_xc[ROWS*DI];          // conv+silu output
__device__ float g_dbl[ROWS*48];         // x_proj output (dt_raw | B | C)
__device__ float g_dt[ROWS*DI];          // softplus dt
__device__ float g_y[ROWS*DI];           // gated scan output
__device__ float g_P[NSEQ*DI*CH*DS];     // per-chunk decay
__device__ float g_H[NSEQ*DI*CH*DS];     // per-chunk end state -> init state

// ---------------- small helpers ----------------
__device__ __forceinline__ unsigned long long pk2(float x, float y){
    unsigned long long r; asm("mov.b64 %0, {%1, %2};" : "=l"(r) : "f"(x), "f"(y)); return r;
}
__device__ __forceinline__ float2 upk2(unsigned long long v){
    float2 f; asm("mov.b64 {%0, %1}, %2;" : "=f"(f.x), "=f"(f.y) : "l"(v)); return f;
}
__device__ __forceinline__ void ffma2(unsigned long long &c, unsigned long long a, unsigned long long b){
    asm("fma.rn.f32x2 %0, %1, %2, %0;" : "+l"(c) : "l"(a), "l"(b));
}
__device__ __forceinline__ float silu_f(float x){ return x / (1.f + expf(-x)); }
__device__ __forceinline__ float softplus_f(float x){ return x > 20.f ? x : log1pf(expf(x)); }

// ---------------- prep: pack (fwd, bwd-reversed) chains into 4 sequences ----------------
__global__ void prep_kernel(const float* __restrict__ x){
    int idx = blockIdx.x*blockDim.x + threadIdx.x;   // ROWS*DM
    int kd  = idx & (DM-1);
    int t   = idx >> 8;
    int l   = t & (L-1);
    int si  = t >> 10;
    int b   = si & 1, c = si >> 1;
    int sl  = c ? (L-1-l) : l;
    g_a0[idx] = x[((size_t)(b*L + sl))*DM + kd];
}

// ---------------- tiled fp32 GEMM, C[r,n] = sum_k A[r,k]*W[n,k], f32x2 FFMA2 core ----------
// asel: 0=g_a0 1=g_a1 2=g_y ; csel: 0=g_a0 1=g_a1 2=g_xz
template<int BN>
__global__ __launch_bounds__(256) void gemm_nt(int asel, const float* __restrict__ Wall,
                                               int csel, int N, int K, int lay)
{
    const float* A    = (asel==0) ? g_a0 : (asel==1) ? g_a1 : g_y;
    float*       Cout = (csel==0) ? g_a0 : (csel==1) ? g_a1 : g_xz;

    constexpr int TPR = 256/BN;     // threads per W row
    constexpr int KPT = BN/16;      // k floats per thread for W tile
    constexpr int TP  = BN/32;      // f32x2 pairs per thread (n dir)

    __shared__ float As[16][68];
    __shared__ float Bs[16][BN];

    int tid = threadIdx.x;
    int r0  = blockIdx.y*64;
    int n0  = blockIdx.x*BN;
    int si  = r0 >> 10;
    int wl  = lay + 2*(si>>1);
    const float* W = Wall + (size_t)wl*N*K;

    int ar = tid>>2, ak = (tid&3)*4;
    int br = tid/TPR, bk = (tid%TPR)*KPT;
    int tx = tid & 15, ty = tid >> 4;

    const float* Ap = A + (size_t)(r0+ar)*K + ak;
    const float* Bp = W + (size_t)(n0+br)*K + bk;

    unsigned long long acc[4][TP];
    #pragma unroll
    for (int i=0;i<4;i++)
        #pragma unroll
        for (int j=0;j<TP;j++) acc[i][j]=0ull;

    for (int k0=0;k0<K;k0+=16){
        float4 av = *(const float4*)(Ap + k0);
        As[ak+0][ar]=av.x; As[ak+1][ar]=av.y; As[ak+2][ar]=av.z; As[ak+3][ar]=av.w;
        #pragma unroll
        for (int v=0; v<KPT/4; v++){
            float4 bv = *(const float4*)(Bp + k0 + 4*v);
            Bs[bk+4*v+0][br]=bv.x; Bs[bk+4*v+1][br]=bv.y;
            Bs[bk+4*v+2][br]=bv.z; Bs[bk+4*v+3][br]=bv.w;
        }
        __syncthreads();
        #pragma unroll
        for (int k=0;k<16;k++){
            float4 a4 = *(const float4*)&As[k][ty*4];
            float am[4] = {a4.x, a4.y, a4.z, a4.w};
            const unsigned long long* bp = (const unsigned long long*)&Bs[k][tx*(TP*2)];
            unsigned long long bb[TP];
            #pragma unroll
            for (int j=0;j<TP;j++) bb[j]=bp[j];
            #pragma unroll
            for (int i=0;i<4;i++){
                unsigned long long ai = pk2(am[i], am[i]);
                #pragma unroll
                for (int j=0;j<TP;j++) ffma2(acc[i][j], ai, bb[j]);
            }
        }
        __syncthreads();
    }
    #pragma unroll
    for (int i=0;i<4;i++){
        int row = r0 + ty*4 + i;
        float* cp = Cout + (size_t)row*N + n0 + tx*(TP*2);
        #pragma unroll
        for (int j=0;j<TP;j++){
            float2 v = upk2(acc[i][j]);
            ((float2*)cp)[j] = v;
        }
    }
}

// ---------------- causal depthwise conv (K=4) + bias + silu ----------------
__global__ void conv_silu(const float* __restrict__ cw, const float* __restrict__ cb, int lay){
    int idx = blockIdx.x*blockDim.x + threadIdx.x;    // ROWS*DI
    int d  = idx & (DI-1);
    int r  = idx >> 9;
    int si = r >> 10;
    int l  = r & (L-1);
    int wl = lay + 2*(si>>1);
    const float* __restrict__ w = cw + (size_t)(wl*DI + d)*4;
    float s = cb[wl*DI + d];
    int base = si*L;
    #pragma unroll
    for (int k=0;k<4;k++){
        int ls = l - 3 + k;
        if (ls >= 0) s = fmaf(g_xz[(size_t)(base+ls)*(2*DI) + d], w[k], s);
    }
    g_xc[idx] = silu_f(s);
}

// ---------------- x_proj: dbl[r, 0..47] = xc[r,:] @ Wx[j,:]  ----------------
__global__ void xproj_kernel(const float* __restrict__ Wx, int lay){
    int r  = blockIdx.x*4 + threadIdx.x/48;   // blockDim = 192
    int j  = threadIdx.x % 48;
    int si = r >> 10;
    int wl = lay + 2*(si>>1);
    const float4* xr = (const float4*)(g_xc + (size_t)r*DI);
    const float4* wr = (const float4*)(Wx + (size_t)(wl*48 + j)*DI);
    float acc = 0.f;
    #pragma unroll 8
    for (int k=0;k<DI/4;k++){
        float4 a = xr[k], b = wr[k];
        acc += a.x*b.x + a.y*b.y + a.z*b.z + a.w*b.w;
    }
    g_dbl[(size_t)r*48 + j] = acc;
}

// ---------------- dt = softplus(dt_raw @ Wdt^T + b) ----------------
__global__ void dt_kernel(const float* __restrict__ Wdt, const float* __restrict__ bdt, int lay){
    int idx = blockIdx.x*blockDim.x + threadIdx.x;   // ROWS*DI
    int d  = idx & (DI-1);
    int r  = idx >> 9;
    int si = r >> 10;
    int wl = lay + 2*(si>>1);
    const float4* dr = (const float4*)(g_dbl + (size_t)r*48);
    const float4* w  = (const float4*)(Wdt + (size_t)(wl*DI + d)*RK);
    float acc = bdt[wl*DI + d];
    #pragma unroll
    for (int q=0;q<RK/4;q++){
        float4 a = dr[q], b = w[q];
        acc += a.x*b.x + a.y*b.y + a.z*b.z + a.w*b.w;
    }
    g_dt[idx] = softplus_f(acc);
}

// ---------------- scan phase 1: chunk-local end state + chunk decay ----------------
__global__ __launch_bounds__(128) void scan_phase1(const float* __restrict__ A_log, int lay){
    int d  = blockIdx.x*128 + threadIdx.x;   // gridDim.x = DI/128 = 4
    int ch = blockIdx.y;                     // 8
    int si = blockIdx.z;                     // 4
    int wl = lay + 2*(si>>1);
    __shared__ float sB[CLEN][DS];
    int rbase = si*L + ch*CLEN;
    for (int i=threadIdx.x; i<CLEN*DS; i+=128){
        int ll = i>>4, s = i&15;
        sB[ll][s] = g_dbl[(size_t)(rbase+ll)*48 + 16 + s];
    }
    __syncthreads();
    float A2[DS], h[DS];
    #pragma unroll
    for (int s=0;s<DS;s++){ A2[s] = -expf(A_log[(size_t)(wl*DI+d)*DS + s]); h[s]=0.f; }
    float sdt = 0.f;
    for (int ll=0; ll<CLEN; ll++){
        int r = rbase + ll;
        float dtc = g_dt[(size_t)r*DI + d];
        float xcv = g_xc[(size_t)r*DI + d];
        float dtx = dtc*xcv;
        sdt += dtc;
        #pragma unroll
        for (int s=0;s<DS;s++){
            float dA = __expf(dtc*A2[s]);
            h[s] = fmaf(dA, h[s], dtx*sB[ll][s]);
        }
    }
    size_t ob = ((size_t)(si*DI + d)*CH + ch)*DS;
    #pragma unroll
    for (int s=0;s<DS;s++){
        g_H[ob+s] = h[s];
        g_P[ob+s] = __expf(sdt*A2[s]);
    }
}

// ---------------- scan combine: serial scan of 8 chunk aggregates ----------------
__global__ void scan_comb(){
    int idx = blockIdx.x*blockDim.x + threadIdx.x;   // NSEQ*DI*DS = 32768
    int s = idx & 15;
    int t = idx >> 4;
    size_t base = (size_t)t*CH*DS + s;
    float run = 0.f;
    #pragma unroll
    for (int c=0;c<CH;c++){
        size_t p = base + (size_t)c*DS;
        float he = g_H[p], pe = g_P[p];
        g_H[p] = run;                 // init state for this chunk
        run = fmaf(pe, run, he);
    }
}

// ---------------- scan phase 2: replay with true init, + xc*D, * silu(z) ----------------
__global__ __launch_bounds__(128) void scan_phase2(const float* __restrict__ A_log,
                                                   const float* __restrict__ Dp, int lay){
    int d  = blockIdx.x*128 + threadIdx.x;
    int ch = blockIdx.y;
    int si = blockIdx.z;
    int wl = lay + 2*(si>>1);
    __shared__ float sB[CLEN][DS];
    __shared__ float sC[CLEN][DS];
    int rbase = si*L + ch*CLEN;
    for (int i=threadIdx.x; i<CLEN*DS; i+=128){
        int ll = i>>4, s = i&15;
        sB[ll][s] = g_dbl[(size_t)(rbase+ll)*48 + 16 + s];
        sC[ll][s] = g_dbl[(size_t)(rbase+ll)*48 + 32 + s];
    }
    __syncthreads();
    float A2[DS], h[DS];
    size_t ib = ((size_t)(si*DI + d)*CH + ch)*DS;
    #pragma unroll
    for (int s=0;s<DS;s++){
        A2[s] = -expf(A_log[(size_t)(wl*DI+d)*DS + s]);
        h[s]  = g_H[ib+s];
    }
    float Dd = Dp[wl*DI + d];
    for (int ll=0; ll<CLEN; ll++){
        int r = rbase + ll;
        float dtc = g_dt[(size_t)r*DI + d];
        float xcv = g_xc[(size_t)r*DI + d];
        float dtx = dtc*xcv;
        #pragma unroll
        for (int s=0;s<DS;s++){
            float dA = __expf(dtc*A2[s]);
            h[s] = fmaf(dA, h[s], dtx*sB[ll][s]);
        }
        float y0=0.f,y1=0.f,y2=0.f,y3=0.f;
        #pragma unroll
        for (int s=0;s<DS;s+=4){
            y0 = fmaf(h[s+0], sC[ll][s+0], y0);
            y1 = fmaf(h[s+1], sC[ll][s+1], y1);
            y2 = fmaf(h[s+2], sC[ll][s+2], y2);
            y3 = fmaf(h[s+3], sC[ll][s+3], y3);
        }
        float y = (y0+y1)+(y2+y3);
        y = fmaf(xcv, Dd, y);
        float z = g_xz[(size_t)r*(2*DI) + DI + d];
        y *= silu_f(z);
        g_y[(size_t)r*DI + d] = y;
    }
}

// ---------------- final: concat fwd + reversed bwd ----------------
__global__ void final_kernel(float* __restrict__ out){
    int idx = blockIdx.x*blockDim.x + threadIdx.x;   // 2*L*DM
    int j = idx & (DM-1);
    int t = idx >> 8;
    int l = t & (L-1);
    int b = t >> 10;
    size_t o = ((size_t)(b*L + l))*(2*DM);
    out[o + j]      = g_a0[((size_t)(b*L + l))*DM + j];
    out[o + DM + j] = g_a0[((size_t)((2+b)*L + (L-1-l)))*DM + j];
}

// ---------------- launch ----------------
extern "C" void kernel_launch(void* const* d_in, const int* in_sizes, int n_in,
                              void* d_out, int out_size)
{
    (void)in_sizes; (void)n_in; (void)out_size;
    const float* x        = (const float*)d_in[0];
    const float* in_proj  = (const float*)d_in[1];
    const float* conv_w   = (const float*)d_in[2];
    const float* conv_b   = (const float*)d_in[3];
    const float* x_proj   = (const float*)d_in[4];
    const float* dt_proj  = (const float*)d_in[5];
    const float* dt_bias  = (const float*)d_in[6];
    const float* A_log    = (const float*)d_in[7];
    const float* Dp       = (const float*)d_in[8];
    const float* out_proj = (const float*)d_in[9];
    float* out = (float*)d_out;

    prep_kernel<<<ROWS*DM/256, 256>>>(x);

    for (int lay = 0; lay < 2; lay++){
        int ain  = lay ? 1 : 0;   // g_a1 : g_a0
        int aout = lay ? 0 : 1;

        // xz = act @ in_proj^T   (N=1024, K=256)
        gemm_nt<128><<<dim3((2*DI)/128, ROWS/64), 256>>>(ain, in_proj, 2, 2*DI, DM, lay);
        conv_silu<<<ROWS*DI/256, 256>>>(conv_w, conv_b, lay);
        xproj_kernel<<<ROWS/4, 192>>>(x_proj, lay);
        dt_kernel<<<ROWS*DI/256, 256>>>(dt_proj, dt_bias, lay);
        scan_phase1<<<dim3(DI/128, CH, NSEQ), 128>>>(A_log, lay);
        scan_comb<<<NSEQ*DI*DS/256, 256>>>();
        scan_phase2<<<dim3(DI/128, CH, NSEQ), 128>>>(A_log, Dp, lay);
        // act_out = y @ out_proj^T  (N=256, K=512)
        gemm_nt<64><<<dim3(DM/64, ROWS/64), 256>>>(2, out_proj, aout, DM, DI, lay);
    }

    final_kernel<<<2*L*DM/256, 256>>>(out);
}

// round 6
// speedup vs baseline: 1.4922x; 1.4922x over previous
#include <cuda_runtime.h>
#include <cstdint>
#include <cstddef>

#define L     1024
#define DM    256
#define DI    512
#define DS    16
#define RK    16
#define NSEQ  4
#define ROWS  (NSEQ*L)      // 4096
#define CH    8
#define CLEN  (L/CH)        // 128

// ---------------- device scratch (static globals: allocation-free) ----------------
__device__ float g_a0[ROWS*DM];          // activation ping
__device__ float g_a1[ROWS*DM];          // activation pong
__device__ float g_xz[ROWS*2*DI];        // in_proj output (xc | z)
__device__ float g_xc[ROWS*DI];          // conv+silu output
__device__ float g_dbl[ROWS*48];         // x_proj output (dt_raw | B | C)
__device__ float g_dt[ROWS*DI];          // softplus dt
__device__ float g_y[ROWS*DI];           // gated scan output
__device__ float g_P[NSEQ*DI*CH*DS];     // per-chunk decay
__device__ float g_H[NSEQ*DI*CH*DS];     // per-chunk end state -> init state

// ---------------- small helpers ----------------
__device__ __forceinline__ unsigned long long pk2(float x, float y){
    unsigned long long r; asm("mov.b64 %0, {%1, %2};" : "=l"(r) : "f"(x), "f"(y)); return r;
}
__device__ __forceinline__ float2 upk2(unsigned long long v){
    float2 f; asm("mov.b64 {%0, %1}, %2;" : "=f"(f.x), "=f"(f.y) : "l"(v)); return f;
}
__device__ __forceinline__ void ffma2(unsigned long long &c, unsigned long long a, unsigned long long b){
    asm("fma.rn.f32x2 %0, %1, %2, %0;" : "+l"(c) : "l"(a), "l"(b));
}
__device__ __forceinline__ float silu_f(float x){ return x / (1.f + expf(-x)); }
__device__ __forceinline__ float softplus_f(float x){ return x > 20.f ? x : log1pf(expf(x)); }

// ---------------- prep: pack (fwd, bwd-reversed) chains into 4 sequences ----------------
__global__ void prep_kernel(const float* __restrict__ x){
    int idx = blockIdx.x*blockDim.x + threadIdx.x;   // ROWS*DM
    int kd  = idx & (DM-1);
    int t   = idx >> 8;
    int l   = t & (L-1);
    int si  = t >> 10;
    int b   = si & 1, c = si >> 1;
    int sl  = c ? (L-1-l) : l;
    g_a0[idx] = x[((size_t)(b*L + sl))*DM + kd];
}

// ============== gemm2: C[r,n] = sum_k A[r,k]*W[n,k] ==============
// 128-row x BN-col block tile, 256 threads (16x16), 8 rows x CN cols per thread.
// Row-pair f32x2 accumulators: A pairs load directly as LDS.128 (ulonglong2),
// only B is duplicated via pk2, hoisted per k for all 4 row-pairs.
// asel: 0=g_a0 1=g_a1 2=g_y ; csel: 0=g_a0 1=g_a1 2=g_xz
template<int BN>
__global__ __launch_bounds__(256) void gemm2(int asel, const float* __restrict__ Wall,
                                             int csel, int N, int K, int lay)
{
    const float* A    = (asel==0) ? g_a0 : (asel==1) ? g_a1 : g_y;
    float*       Cout = (csel==0) ? g_a0 : (csel==1) ? g_a1 : g_xz;

    constexpr int CN  = BN/16;            // cols per thread (8 or 4)
    constexpr int BL4 = BN*4;             // float4 count of B tile (BN rows x 16 k)

    __shared__ float As[16][132];         // [k][row], +4 pad
    __shared__ float Bs[16][BN+4];        // [k][col]

    int tid = threadIdx.x;
    int tx  = tid & 15, ty = tid >> 4;
    int r0  = blockIdx.y*128;
    int n0  = blockIdx.x*BN;
    int si  = r0 >> 10;
    int wl  = lay + 2*(si>>1);
    const float* W = Wall + (size_t)wl*N*K;

    unsigned long long acc[4][CN];
    #pragma unroll
    for (int p=0;p<4;p++)
        #pragma unroll
        for (int c=0;c<CN;c++) acc[p][c]=0ull;

    // global->smem mapping: i -> (row = i>>2, kq = i&3), float4 along k
    int ra = (tid>>2), ka = (tid&3)*4;

    for (int k0=0; k0<K; k0+=16){
        // A tile: 128 rows x 16 k = 512 float4, 2 per thread
        #pragma unroll
        for (int it=0; it<2; it++){
            int r = ra + it*64;
            float4 v = *(const float4*)(A + (size_t)(r0+r)*K + k0 + ka);
            As[ka+0][r]=v.x; As[ka+1][r]=v.y; As[ka+2][r]=v.z; As[ka+3][r]=v.w;
        }
        // B tile: BN rows x 16 k
        #pragma unroll
        for (int it=0; it<BL4/256; it++){
            int n = ra + it*64;
            float4 v = *(const float4*)(W + (size_t)(n0+n)*K + k0 + ka);
            Bs[ka+0][n]=v.x; Bs[ka+1][n]=v.y; Bs[ka+2][n]=v.z; Bs[ka+3][n]=v.w;
        }
        __syncthreads();
        #pragma unroll
        for (int k=0;k<16;k++){
            ulonglong2 a01 = *(const ulonglong2*)&As[k][ty*8];
            ulonglong2 a23 = *(const ulonglong2*)&As[k][ty*8+4];
            float bv[CN];
            #pragma unroll
            for (int v4=0; v4<CN/4; v4++){
                float4 b4 = *(const float4*)&Bs[k][tx*CN + v4*4];
                bv[v4*4+0]=b4.x; bv[v4*4+1]=b4.y; bv[v4*4+2]=b4.z; bv[v4*4+3]=b4.w;
            }
            #pragma unroll
            for (int c=0;c<CN;c++){
                unsigned long long bb = pk2(bv[c], bv[c]);
                ffma2(acc[0][c], a01.x, bb);
                ffma2(acc[1][c], a01.y, bb);
                ffma2(acc[2][c], a23.x, bb);
                ffma2(acc[3][c], a23.y, bb);
            }
        }
        __syncthreads();
    }
    // store: pair p covers rows (ty*8+2p, ty*8+2p+1)
    #pragma unroll
    for (int p=0;p<4;p++){
        float lo[CN], hi[CN];
        #pragma unroll
        for (int c=0;c<CN;c++){ float2 v = upk2(acc[p][c]); lo[c]=v.x; hi[c]=v.y; }
        float* c0 = Cout + (size_t)(r0 + ty*8 + 2*p)*N + n0 + tx*CN;
        float* c1 = c0 + N;
        #pragma unroll
        for (int v4=0; v4<CN/4; v4++){
            ((float4*)c0)[v4] = make_float4(lo[4*v4],lo[4*v4+1],lo[4*v4+2],lo[4*v4+3]);
            ((float4*)c1)[v4] = make_float4(hi[4*v4],hi[4*v4+1],hi[4*v4+2],hi[4*v4+3]);
        }
    }
}

// ============== xproj2: dbl[4096x48] = xc[4096x512] @ Wx^T, smem-tiled ==============
// 32 rows/block (grid 128), K-chunks of 128. cols per thread: c = tx + 16q (q<3) -> 48 exact.
// rows per thread: ty*2, ty*2+1. All smem reads broadcast or lane-consecutive (conflict-free).
__global__ __launch_bounds__(256) void xproj2(const float* __restrict__ Wx, int lay){
    __shared__ float sA[128][33];   // [k][row 0..31], pad 33
    __shared__ float sW[128][49];   // [k][col 0..47], pad 49

    int tid = threadIdx.x;
    int tx  = tid & 15, ty = tid >> 4;
    int r0  = blockIdx.x*32;
    int si  = r0 >> 10;
    int wl  = lay + 2*(si>>1);
    const float* Wb = Wx + (size_t)wl*48*DI;

    float acc[2][3];
    #pragma unroll
    for (int i=0;i<2;i++){ acc[i][0]=0.f; acc[i][1]=0.f; acc[i][2]=0.f; }

    for (int k0=0; k0<DI; k0+=128){
        // A tile: 32 rows x 128 k = 1024 float4, 4/thread: r = i>>5, kq = i&31
        #pragma unroll
        for (int it=0; it<4; it++){
            int i = tid + it*256;
            int r = i >> 5, kq = i & 31;
            float4 v = *(const float4*)(g_xc + (size_t)(r0+r)*DI + k0 + kq*4);
            sA[kq*4+0][r]=v.x; sA[kq*4+1][r]=v.y; sA[kq*4+2][r]=v.z; sA[kq*4+3][r]=v.w;
        }
        // W tile: 48 rows(j) x 128 k = 1536 float4, 6/thread: j = i>>5, kq = i&31
        #pragma unroll
        for (int it=0; it<6; it++){
            int i = tid + it*256;
            int j = i >> 5, kq = i & 31;
            float4 v = *(const float4*)(Wb + (size_t)j*DI + k0 + kq*4);
            sW[kq*4+0][j]=v.x; sW[kq*4+1][j]=v.y; sW[kq*4+2][j]=v.z; sW[kq*4+3][j]=v.w;
        }
        __syncthreads();
        #pragma unroll 4
        for (int k=0;k<128;k++){
            float a0 = sA[k][ty*2], a1 = sA[k][ty*2+1];
            float b0 = sW[k][tx], b1 = sW[k][tx+16], b2 = sW[k][tx+32];
            acc[0][0] = fmaf(a0,b0,acc[0][0]);
            acc[0][1] = fmaf(a0,b1,acc[0][1]);
            acc[0][2] = fmaf(a0,b2,acc[0][2]);
            acc[1][0] = fmaf(a1,b0,acc[1][0]);
            acc[1][1] = fmaf(a1,b1,acc[1][1]);
            acc[1][2] = fmaf(a1,b2,acc[1][2]);
        }
        __syncthreads();
    }
    #pragma unroll
    for (int i=0;i<2;i++){
        float* dp = g_dbl + (size_t)(r0 + ty*2 + i)*48;
        dp[tx]    = acc[i][0];
        dp[tx+16] = acc[i][1];
        dp[tx+32] = acc[i][2];
    }
}

// ---------------- causal depthwise conv (K=4) + bias + silu ----------------
__global__ void conv_silu(const float* __restrict__ cw, const float* __restrict__ cb, int lay){
    int idx = blockIdx.x*blockDim.x + threadIdx.x;    // ROWS*DI
    int d  = idx & (DI-1);
    int r  = idx >> 9;
    int si = r >> 10;
    int l  = r & (L-1);
    int wl = lay + 2*(si>>1);
    const float* __restrict__ w = cw + (size_t)(wl*DI + d)*4;
    float s = cb[wl*DI + d];
    int base = si*L;
    #pragma unroll
    for (int k=0;k<4;k++){
        int ls = l - 3 + k;
        if (ls >= 0) s = fmaf(g_xz[(size_t)(base+ls)*(2*DI) + d], w[k], s);
    }
    g_xc[idx] = silu_f(s);
}

// ---------------- dt = softplus(dt_raw @ Wdt^T + b) ----------------
__global__ void dt_kernel(const float* __restrict__ Wdt, const float* __restrict__ bdt, int lay){
    int idx = blockIdx.x*blockDim.x + threadIdx.x;   // ROWS*DI
    int d  = idx & (DI-1);
    int r  = idx >> 9;
    int si = r >> 10;
    int wl = lay + 2*(si>>1);
    const float4* dr = (const float4*)(g_dbl + (size_t)r*48);
    const float4* w  = (const float4*)(Wdt + (size_t)(wl*DI + d)*RK);
    float acc = bdt[wl*DI + d];
    #pragma unroll
    for (int q=0;q<RK/4;q++){
        float4 a = dr[q], b = w[q];
        acc += a.x*b.x + a.y*b.y + a.z*b.z + a.w*b.w;
    }
    g_dt[idx] = softplus_f(acc);
}

// ---------------- scan phase 1: chunk-local end state + chunk decay ----------------
__global__ __launch_bounds__(128) void scan_phase1(const float* __restrict__ A_log, int lay){
    int d  = blockIdx.x*128 + threadIdx.x;   // gridDim.x = DI/128 = 4
    int ch = blockIdx.y;                     // 8
    int si = blockIdx.z;                     // 4
    int wl = lay + 2*(si>>1);
    __shared__ float sB[CLEN][DS];
    int rbase = si*L + ch*CLEN;
    for (int i=threadIdx.x; i<CLEN*DS; i+=128){
        int ll = i>>4, s = i&15;
        sB[ll][s] = g_dbl[(size_t)(rbase+ll)*48 + 16 + s];
    }
    __syncthreads();
    float A2[DS], h[DS];
    #pragma unroll
    for (int s=0;s<DS;s++){ A2[s] = -expf(A_log[(size_t)(wl*DI+d)*DS + s]); h[s]=0.f; }
    float sdt = 0.f;
    for (int ll=0; ll<CLEN; ll++){
        int r = rbase + ll;
        float dtc = g_dt[(size_t)r*DI + d];
        float xcv = g_xc[(size_t)r*DI + d];
        float dtx = dtc*xcv;
        sdt += dtc;
        #pragma unroll
        for (int s=0;s<DS;s++){
            float dA = __expf(dtc*A2[s]);
            h[s] = fmaf(dA, h[s], dtx*sB[ll][s]);
        }
    }
    size_t ob = ((size_t)(si*DI + d)*CH + ch)*DS;
    #pragma unroll
    for (int s=0;s<DS;s++){
        g_H[ob+s] = h[s];
        g_P[ob+s] = __expf(sdt*A2[s]);
    }
}

// ---------------- scan combine: serial scan of 8 chunk aggregates ----------------
__global__ void scan_comb(){
    int idx = blockIdx.x*blockDim.x + threadIdx.x;   // NSEQ*DI*DS = 32768
    int s = idx & 15;
    int t = idx >> 4;
    size_t base = (size_t)t*CH*DS + s;
    float run = 0.f;
    #pragma unroll
    for (int c=0;c<CH;c++){
        size_t p = base + (size_t)c*DS;
        float he = g_H[p], pe = g_P[p];
        g_H[p] = run;                 // init state for this chunk
        run = fmaf(pe, run, he);
    }
}

// ---------------- scan phase 2: replay with true init, + xc*D, * silu(z) ----------------
__global__ __launch_bounds__(128) void scan_phase2(const float* __restrict__ A_log,
                                                   const float* __restrict__ Dp, int lay){
    int d  = blockIdx.x*128 + threadIdx.x;
    int ch = blockIdx.y;
    int si = blockIdx.z;
    int wl = lay + 2*(si>>1);
    __shared__ float sB[CLEN][DS];
    __shared__ float sC[CLEN][DS];
    int rbase = si*L + ch*CLEN;
    for (int i=threadIdx.x; i<CLEN*DS; i+=128){
        int ll = i>>4, s = i&15;
        sB[ll][s] = g_dbl[(size_t)(rbase+ll)*48 + 16 + s];
        sC[ll][s] = g_dbl[(size_t)(rbase+ll)*48 + 32 + s];
    }
    __syncthreads();
    float A2[DS], h[DS];
    size_t ib = ((size_t)(si*DI + d)*CH + ch)*DS;
    #pragma unroll
    for (int s=0;s<DS;s++){
        A2[s] = -expf(A_log[(size_t)(wl*DI+d)*DS + s]);
        h[s]  = g_H[ib+s];
    }
    float Dd = Dp[wl*DI + d];
    for (int ll=0; ll<CLEN; ll++){
        int r = rbase + ll;
        float dtc = g_dt[(size_t)r*DI + d];
        float xcv = g_xc[(size_t)r*DI + d];
        float dtx = dtc*xcv;
        #pragma unroll
        for (int s=0;s<DS;s++){
            float dA = __expf(dtc*A2[s]);
            h[s] = fmaf(dA, h[s], dtx*sB[ll][s]);
        }
        float y0=0.f,y1=0.f,y2=0.f,y3=0.f;
        #pragma unroll
        for (int s=0;s<DS;s+=4){
            y0 = fmaf(h[s+0], sC[ll][s+0], y0);
            y1 = fmaf(h[s+1], sC[ll][s+1], y1);
            y2 = fmaf(h[s+2], sC[ll][s+2], y2);
            y3 = fmaf(h[s+3], sC[ll][s+3], y3);
        }
        float y = (y0+y1)+(y2+y3);
        y = fmaf(xcv, Dd, y);
        float z = g_xz[(size_t)r*(2*DI) + DI + d];
        y *= silu_f(z);
        g_y[(size_t)r*DI + d] = y;
    }
}

// ---------------- final: concat fwd + reversed bwd ----------------
__global__ void final_kernel(float* __restrict__ out){
    int idx = blockIdx.x*blockDim.x + threadIdx.x;   // 2*L*DM
    int j = idx & (DM-1);
    int t = idx >> 8;
    int l = t & (L-1);
    int b = t >> 10;
    size_t o = ((size_t)(b*L + l))*(2*DM);
    out[o + j]      = g_a0[((size_t)(b*L + l))*DM + j];
    out[o + DM + j] = g_a0[((size_t)((2+b)*L + (L-1-l)))*DM + j];
}

// ---------------- launch ----------------
extern "C" void kernel_launch(void* const* d_in, const int* in_sizes, int n_in,
                              void* d_out, int out_size)
{
    (void)in_sizes; (void)n_in; (void)out_size;
    const float* x        = (const float*)d_in[0];
    const float* in_proj  = (const float*)d_in[1];
    const float* conv_w   = (const float*)d_in[2];
    const float* conv_b   = (const float*)d_in[3];
    const float* x_proj   = (const float*)d_in[4];
    const float* dt_proj  = (const float*)d_in[5];
    const float* dt_bias  = (const float*)d_in[6];
    const float* A_log    = (const float*)d_in[7];
    const float* Dp       = (const float*)d_in[8];
    const float* out_proj = (const float*)d_in[9];
    float* out = (float*)d_out;

    prep_kernel<<<ROWS*DM/256, 256>>>(x);

    for (int lay = 0; lay < 2; lay++){
        int ain  = lay ? 1 : 0;   // g_a1 : g_a0
        int aout = lay ? 0 : 1;

        // xz = act @ in_proj^T   (N=1024, K=256), 128x128 tiles
        gemm2<128><<<dim3((2*DI)/128, ROWS/128), 256>>>(ain, in_proj, 2, 2*DI, DM, lay);
        conv_silu<<<ROWS*DI/256, 256>>>(conv_w, conv_b, lay);
        xproj2<<<ROWS/32, 256>>>(x_proj, lay);
        dt_kernel<<<ROWS*DI/256, 256>>>(dt_proj, dt_bias, lay);
        scan_phase1<<<dim3(DI/128, CH, NSEQ), 128>>>(A_log, lay);
        scan_comb<<<NSEQ*DI*DS/256, 256>>>();
        scan_phase2<<<dim3(DI/128, CH, NSEQ), 128>>>(A_log, Dp, lay);
        // act_out = y @ out_proj^T  (N=256, K=512), 128x64 tiles
        gemm2<64><<<dim3(DM/64, ROWS/128), 256>>>(2, out_proj, aout, DM, DI, lay);
    }

    final_kernel<<<2*L*DM/256, 256>>>(out);
}

// round 7
// speedup vs baseline: 1.9159x; 1.2840x over previous
#include <cuda_runtime.h>
#include <cstdint>
#include <cstddef>

#define L     1024
#define DM    256
#define DI    512
#define DS    16
#define RK    16
#define NSEQ  4
#define ROWS  (NSEQ*L)      // 4096
#define CH    16
#define CLEN  (L/CH)        // 64

typedef unsigned long long ull;

// ---------------- device scratch ----------------
__device__ float g_a1[ROWS*DM];          // inter-layer activation
__device__ float g_xz[ROWS*2*DI];        // in_proj output (xc | z)
__device__ float g_xc[ROWS*DI];          // conv+silu output
__device__ float g_dblp[2][ROWS*48];     // x_proj partial outputs (k-split)
__device__ float g_dt[ROWS*DI];          // softplus dt
__device__ float g_y[ROWS*DI];           // gated scan output
__device__ float g_P[NSEQ*DI*CH*DS];     // per-chunk decay
__device__ float g_H[NSEQ*DI*CH*DS];     // per-chunk end state -> init state

// ---------------- helpers ----------------
__device__ __forceinline__ ull pk2(float x, float y){
    ull r; asm("mov.b64 %0, {%1, %2};" : "=l"(r) : "f"(x), "f"(y)); return r;
}
__device__ __forceinline__ float2 upk2(ull v){
    float2 f; asm("mov.b64 {%0, %1}, %2;" : "=f"(f.x), "=f"(f.y) : "l"(v)); return f;
}
__device__ __forceinline__ void ffma2(ull &c, ull a, ull b){
    asm("fma.rn.f32x2 %0, %1, %2, %0;" : "+l"(c) : "l"(a), "l"(b));
}
__device__ __forceinline__ float ex2f(float x){
    float r; asm("ex2.approx.ftz.f32 %0, %1;" : "=f"(r) : "f"(x)); return r;
}
#define LOG2E 1.4426950408889634f
__device__ __forceinline__ float silu_f(float x){ return x / (1.f + ex2f(-LOG2E*x)); }
__device__ __forceinline__ float softplus_f(float x){ return x > 20.f ? x : log1pf(expf(x)); }

// row remap helpers (prep / final fused into GEMM)
__device__ __forceinline__ const float* arow(const float* Abase, int asel, int rr, int K,
                                             const float* xp){
    if (asel == 3){
        int sio = rr>>10, b = sio&1, c = sio>>1, l = rr&(L-1);
        return xp + ((size_t)(b*L + (c ? (L-1-l) : l)))*DM;
    }
    return Abase + (size_t)rr*K;
}
__device__ __forceinline__ float* crow(float* Cbase, int csel, int rr, int N, float* outp){
    if (csel == 3){
        int sio = rr>>10, b = sio&1, c = sio>>1, l = rr&(L-1);
        return outp + ((size_t)(b*L + (c ? (L-1-l) : l)))*(2*DM) + c*DM;
    }
    return Cbase + (size_t)rr*N;
}

// ============== gemm2: C[r,n] = sum_k A[r,k]*W[n,k] ==============
// BM x BN block tile, 256 threads (16x16). Row-pair f32x2 accumulators.
// asel: 1=g_a1 2=g_y 3=x(remap) ; csel: 1=g_a1 2=g_xz 3=out(remap)
template<int BM, int BN>
__global__ __launch_bounds__(256) void gemm2(int asel, const float* __restrict__ Wall,
                                             int csel, int N, int K, int lay,
                                             const float* __restrict__ xin,
                                             float* __restrict__ outp)
{
    const float* A    = (asel==1) ? g_a1 : g_y;   // asel==3 handled in arow
    float*       Cout = (csel==1) ? g_a1 : g_xz;

    constexpr int RT = BM/16;             // rows per thread
    constexpr int NP = RT/2;              // row pairs per thread
    constexpr int CN = BN/16;             // cols per thread

    __shared__ float As[16*(BM+4)];
    __shared__ float Bs[16*(BN+4)];

    int tid = threadIdx.x;
    int tx  = tid & 15, ty = tid >> 4;
    int r0  = blockIdx.y*BM;
    int n0  = blockIdx.x*BN;
    int si  = r0 >> 10;
    int wl  = lay + 2*(si>>1);
    const float* W = Wall + (size_t)wl*N*K;

    ull acc[NP][CN];
    #pragma unroll
    for (int p=0;p<NP;p++)
        #pragma unroll
        for (int c=0;c<CN;c++) acc[p][c]=0ull;

    int ra = (tid>>2), ka = (tid&3)*4;

    for (int k0=0; k0<K; k0+=16){
        #pragma unroll
        for (int it=0; it<BM/64; it++){
            int r = ra + it*64;
            const float* ap = arow(A, asel, r0+r, K, xin);
            float4 v = *(const float4*)(ap + k0 + ka);
            As[(ka+0)*(BM+4)+r]=v.x; As[(ka+1)*(BM+4)+r]=v.y;
            As[(ka+2)*(BM+4)+r]=v.z; As[(ka+3)*(BM+4)+r]=v.w;
        }
        #pragma unroll
        for (int it=0; it<BN/64; it++){
            int n = ra + it*64;
            float4 v = *(const float4*)(W + (size_t)(n0+n)*K + k0 + ka);
            Bs[(ka+0)*(BN+4)+n]=v.x; Bs[(ka+1)*(BN+4)+n]=v.y;
            Bs[(ka+2)*(BN+4)+n]=v.z; Bs[(ka+3)*(BN+4)+n]=v.w;
        }
        __syncthreads();
        #pragma unroll
        for (int k=0;k<16;k++){
            const ull* ap = (const ull*)&As[k*(BM+4) + ty*RT];
            ull av[NP];
            #pragma unroll
            for (int p=0;p<NP;p++) av[p]=ap[p];
            float bv[CN];
            #pragma unroll
            for (int v4=0; v4<CN/4; v4++){
                float4 b4 = *(const float4*)&Bs[k*(BN+4) + tx*CN + v4*4];
                bv[v4*4+0]=b4.x; bv[v4*4+1]=b4.y; bv[v4*4+2]=b4.z; bv[v4*4+3]=b4.w;
            }
            #pragma unroll
            for (int c=0;c<CN;c++){
                ull bb = pk2(bv[c], bv[c]);
                #pragma unroll
                for (int p=0;p<NP;p++) ffma2(acc[p][c], av[p], bb);
            }
        }
        __syncthreads();
    }
    #pragma unroll
    for (int p=0;p<NP;p++){
        float lo[CN], hi[CN];
        #pragma unroll
        for (int c=0;c<CN;c++){ float2 v = upk2(acc[p][c]); lo[c]=v.x; hi[c]=v.y; }
        float* c0 = crow(Cout, csel, r0 + ty*RT + 2*p,     N, outp) + n0 + tx*CN;
        float* c1 = crow(Cout, csel, r0 + ty*RT + 2*p + 1, N, outp) + n0 + tx*CN;
        #pragma unroll
        for (int v4=0; v4<CN/4; v4++){
            ((float4*)c0)[v4] = make_float4(lo[4*v4],lo[4*v4+1],lo[4*v4+2],lo[4*v4+3]);
            ((float4*)c1)[v4] = make_float4(hi[4*v4],hi[4*v4+1],hi[4*v4+2],hi[4*v4+3]);
        }
    }
}

// ============== xproj3: fused conv+silu + dbl = xc @ Wx^T (k-split x2) ==============
// 32 rows/block, K half per blockIdx.y (256 k each, 2 chunks of 128).
// A-tile loader computes xc = silu(conv(xz)+b) inline and writes g_xc.
// Inner loop: 64-bit LDS + FFMA2 pairs. Layout [row][k], stride 130 (conflict-free LDS.64).
__global__ __launch_bounds__(256) void xproj3(const float* __restrict__ Wx,
                                              const float* __restrict__ cw,
                                              const float* __restrict__ cb, int lay){
    __shared__ float sA[32*130];
    __shared__ float sW[48*130];

    int tid = threadIdx.x;
    int tx  = tid & 15, ty = tid >> 4;
    int r0  = blockIdx.x*32;
    int kh  = blockIdx.y;            // k half: [kh*256, kh*256+256)
    int si  = r0 >> 10;
    int wl  = lay + 2*(si>>1);
    const float* Wb  = Wx + (size_t)wl*48*DI;
    const float* cwb = cw + (size_t)wl*DI*4;
    const float* cbb = cb + (size_t)wl*DI;

    ull acc[2][3];
    #pragma unroll
    for (int i=0;i<2;i++){ acc[i][0]=0ull; acc[i][1]=0ull; acc[i][2]=0ull; }

    for (int kc=0; kc<2; kc++){
        int k0 = kh*256 + kc*128;
        // A tile via fused conv+silu: 32 rows x 128 d
        #pragma unroll
        for (int it=0; it<4; it++){
            int i = tid + it*256;            // 0..1023
            int r = i>>5, q = i&31;
            int rr = r0 + r, l = rr & (L-1);
            int d0 = k0 + q*4;
            const float* xp = g_xz + (size_t)rr*(2*DI) + d0;
            float4 z4 = make_float4(0.f,0.f,0.f,0.f);
            float4 v0 = (l>=3) ? *(const float4*)(xp - 3*(2*DI)) : z4;
            float4 v1 = (l>=2) ? *(const float4*)(xp - 2*(2*DI)) : z4;
            float4 v2 = (l>=1) ? *(const float4*)(xp - 1*(2*DI)) : z4;
            float4 v3 = *(const float4*)(xp);
            float4 w0 = *(const float4*)(cwb + (size_t)d0*4);
            float4 w1 = *(const float4*)(cwb + (size_t)d0*4 + 4);
            float4 w2 = *(const float4*)(cwb + (size_t)d0*4 + 8);
            float4 w3 = *(const float4*)(cwb + (size_t)d0*4 + 12);
            float4 bb = *(const float4*)(cbb + d0);
            float s0 = bb.x + v0.x*w0.x + v1.x*w0.y + v2.x*w0.z + v3.x*w0.w;
            float s1 = bb.y + v0.y*w1.x + v1.y*w1.y + v2.y*w1.z + v3.y*w1.w;
            float s2 = bb.z + v0.z*w2.x + v1.z*w2.y + v2.z*w2.z + v3.z*w2.w;
            float s3 = bb.w + v0.w*w3.x + v1.w*w3.y + v2.w*w3.z + v3.w*w3.w;
            s0 = silu_f(s0); s1 = silu_f(s1); s2 = silu_f(s2); s3 = silu_f(s3);
            float* ap = &sA[r*130 + q*4];
            ap[0]=s0; ap[1]=s1; ap[2]=s2; ap[3]=s3;
            *(float4*)(g_xc + (size_t)rr*DI + d0) = make_float4(s0,s1,s2,s3);
        }
        // W tile: 48 x 128
        #pragma unroll
        for (int it=0; it<6; it++){
            int i = tid + it*256;            // 0..1535
            int j = i>>5, q = i&31;
            float4 v = *(const float4*)(Wb + (size_t)j*DI + k0 + q*4);
            float* wp = &sW[j*130 + q*4];
            wp[0]=v.x; wp[1]=v.y; wp[2]=v.z; wp[3]=v.w;
        }
        __syncthreads();
        const ull* a0p = (const ull*)&sA[(ty*2  )*130];
        const ull* a1p = (const ull*)&sA[(ty*2+1)*130];
        const ull* w0p = (const ull*)&sW[(tx    )*130];
        const ull* w1p = (const ull*)&sW[(tx+16 )*130];
        const ull* w2p = (const ull*)&sW[(tx+32 )*130];
        #pragma unroll 8
        for (int k2=0;k2<64;k2++){
            ull a0=a0p[k2], a1=a1p[k2];
            ull b0=w0p[k2], b1=w1p[k2], b2=w2p[k2];
            ffma2(acc[0][0],a0,b0); ffma2(acc[0][1],a0,b1); ffma2(acc[0][2],a0,b2);
            ffma2(acc[1][0],a1,b0); ffma2(acc[1][1],a1,b1); ffma2(acc[1][2],a1,b2);
        }
        __syncthreads();
    }
    #pragma unroll
    for (int i=0;i<2;i++){
        int rr = r0 + ty*2 + i;
        float* dp = g_dblp[kh] + (size_t)rr*48;
        float2 v0=upk2(acc[i][0]), v1=upk2(acc[i][1]), v2=upk2(acc[i][2]);
        dp[tx]    = v0.x+v0.y;
        dp[tx+16] = v1.x+v1.y;
        dp[tx+32] = v2.x+v2.y;
    }
}

// ---------------- dt = softplus((p0+p1)[0:16] @ Wdt^T + b) ----------------
__global__ void dt_kernel(const float* __restrict__ Wdt, const float* __restrict__ bdt, int lay){
    int idx = blockIdx.x*blockDim.x + threadIdx.x;   // ROWS*DI
    int d  = idx & (DI-1);
    int r  = idx >> 9;
    int si = r >> 10;
    int wl = lay + 2*(si>>1);
    const float4* d0 = (const float4*)(g_dblp[0] + (size_t)r*48);
    const float4* d1 = (const float4*)(g_dblp[1] + (size_t)r*48);
    const float4* w  = (const float4*)(Wdt + (size_t)(wl*DI + d)*RK);
    float acc = bdt[wl*DI + d];
    #pragma unroll
    for (int q=0;q<RK/4;q++){
        float4 a = d0[q], a2 = d1[q], b = w[q];
        acc += (a.x+a2.x)*b.x + (a.y+a2.y)*b.y + (a.z+a2.z)*b.z + (a.w+a2.w)*b.w;
    }
    g_dt[idx] = softplus_f(acc);
}

// ---------------- scan phase 1: chunk-local end state + chunk decay ----------------
__global__ __launch_bounds__(128) void scan_phase1(const float* __restrict__ A_log, int lay){
    int d  = blockIdx.x*128 + threadIdx.x;   // gridDim.x = 4
    int ch = blockIdx.y;                     // 16
    int si = blockIdx.z;                     // 4
    int wl = lay + 2*(si>>1);
    __shared__ float sB[CLEN][DS];
    int rbase = si*L + ch*CLEN;
    for (int i=threadIdx.x; i<CLEN*DS; i+=128){
        int ll = i>>4, s = i&15;
        size_t off = (size_t)(rbase+ll)*48 + 16 + s;
        sB[ll][s] = g_dblp[0][off] + g_dblp[1][off];
    }
    __syncthreads();
    float A2[DS], h[DS];
    #pragma unroll
    for (int s=0;s<DS;s++){
        A2[s] = -expf(A_log[(size_t)(wl*DI+d)*DS + s]) * LOG2E;
        h[s]=0.f;
    }
    float sdt = 0.f;
    for (int ll=0; ll<CLEN; ll++){
        int r = rbase + ll;
        float dtc = g_dt[(size_t)r*DI + d];
        float xcv = g_xc[(size_t)r*DI + d];
        float dtx = dtc*xcv;
        sdt += dtc;
        #pragma unroll
        for (int s=0;s<DS;s++){
            float dA = ex2f(dtc*A2[s]);
            h[s] = fmaf(dA, h[s], dtx*sB[ll][s]);
        }
    }
    size_t ob = ((size_t)(si*DI + d)*CH + ch)*DS;
    #pragma unroll
    for (int s=0;s<DS;s++){
        g_H[ob+s] = h[s];
        g_P[ob+s] = ex2f(sdt*A2[s]);
    }
}

// ---------------- scan combine: serial scan of 16 chunk aggregates ----------------
__global__ void scan_comb(){
    int idx = blockIdx.x*blockDim.x + threadIdx.x;   // NSEQ*DI*DS = 32768
    int s = idx & 15;
    int t = idx >> 4;
    size_t base = (size_t)t*CH*DS + s;
    float run = 0.f;
    #pragma unroll
    for (int c=0;c<CH;c++){
        size_t p = base + (size_t)c*DS;
        float he = g_H[p], pe = g_P[p];
        g_H[p] = run;
        run = fmaf(pe, run, he);
    }
}

// ---------------- scan phase 2: replay with true init, + xc*D, * silu(z) ----------------
__global__ __launch_bounds__(128) void scan_phase2(const float* __restrict__ A_log,
                                                   const float* __restrict__ Dp, int lay){
    int d  = blockIdx.x*128 + threadIdx.x;
    int ch = blockIdx.y;
    int si = blockIdx.z;
    int wl = lay + 2*(si>>1);
    __shared__ float sB[CLEN][DS];
    __shared__ float sC[CLEN][DS];
    int rbase = si*L + ch*CLEN;
    for (int i=threadIdx.x; i<CLEN*DS; i+=128){
        int ll = i>>4, s = i&15;
        size_t off = (size_t)(rbase+ll)*48 + 16 + s;
        sB[ll][s] = g_dblp[0][off]    + g_dblp[1][off];
        sC[ll][s] = g_dblp[0][off+16] + g_dblp[1][off+16];
    }
    __syncthreads();
    float A2[DS], h[DS];
    size_t ib = ((size_t)(si*DI + d)*CH + ch)*DS;
    #pragma unroll
    for (int s=0;s<DS;s++){
        A2[s] = -expf(A_log[(size_t)(wl*DI+d)*DS + s]) * LOG2E;
        h[s]  = g_H[ib+s];
    }
    float Dd = Dp[wl*DI + d];
    for (int ll=0; ll<CLEN; ll++){
        int r = rbase + ll;
        float dtc = g_dt[(size_t)r*DI + d];
        float xcv = g_xc[(size_t)r*DI + d];
        float dtx = dtc*xcv;
        #pragma unroll
        for (int s=0;s<DS;s++){
            float dA = ex2f(dtc*A2[s]);
            h[s] = fmaf(dA, h[s], dtx*sB[ll][s]);
        }
        float y0=0.f,y1=0.f,y2=0.f,y3=0.f;
        #pragma unroll
        for (int s=0;s<DS;s+=4){
            y0 = fmaf(h[s+0], sC[ll][s+0], y0);
            y1 = fmaf(h[s+1], sC[ll][s+1], y1);
            y2 = fmaf(h[s+2], sC[ll][s+2], y2);
            y3 = fmaf(h[s+3], sC[ll][s+3], y3);
        }
        float y = (y0+y1)+(y2+y3);
        y = fmaf(xcv, Dd, y);
        float z = g_xz[(size_t)r*(2*DI) + DI + d];
        y *= silu_f(z);
        g_y[(size_t)r*DI + d] = y;
    }
}

// ---------------- launch ----------------
extern "C" void kernel_launch(void* const* d_in, const int* in_sizes, int n_in,
                              void* d_out, int out_size)
{
    (void)in_sizes; (void)n_in; (void)out_size;
    const float* x        = (const float*)d_in[0];
    const float* in_proj  = (const float*)d_in[1];
    const float* conv_w   = (const float*)d_in[2];
    const float* conv_b   = (const float*)d_in[3];
    const float* x_proj   = (const float*)d_in[4];
    const float* dt_proj  = (const float*)d_in[5];
    const float* dt_bias  = (const float*)d_in[6];
    const float* A_log    = (const float*)d_in[7];
    const float* Dp       = (const float*)d_in[8];
    const float* out_proj = (const float*)d_in[9];
    float* out = (float*)d_out;

    for (int lay = 0; lay < 2; lay++){
        int ain  = lay ? 1 : 3;        // layer0 reads x with prep-remap, layer1 reads g_a1
        int cout = lay ? 3 : 1;        // layer1 writes out with final-remap, layer0 -> g_a1

        // xz = act @ in_proj^T   (N=1024, K=256)
        gemm2<128,128><<<dim3((2*DI)/128, ROWS/128), 256>>>(ain, in_proj, 2, 2*DI, DM, lay, x, nullptr);
        // conv+silu fused into xproj A-load; writes g_xc + g_dblp[0/1]
        xproj3<<<dim3(ROWS/32, 2), 256>>>(x_proj, conv_w, conv_b, lay);
        dt_kernel<<<ROWS*DI/256, 256>>>(dt_proj, dt_bias, lay);
        scan_phase1<<<dim3(DI/128, CH, NSEQ), 128>>>(A_log, lay);
        scan_comb<<<NSEQ*DI*DS/256, 256>>>();
        scan_phase2<<<dim3(DI/128, CH, NSEQ), 128>>>(A_log, Dp, lay);
        // act_out = y @ out_proj^T  (N=256, K=512), 64x64 tiles -> grid 256
        gemm2<64,64><<<dim3(DM/64, ROWS/64), 256>>>(2, out_proj, cout, DM, DI, lay, nullptr, out);
    }
}

// round 8
// speedup vs baseline: 1.9587x; 1.0224x over previous
#include <cuda_runtime.h>
#include <cstdint>
#include <cstddef>

#define L     1024
#define DM    256
#define DI    512
#define DS    16
#define RK    16
#define NSEQ  4
#define ROWS  (NSEQ*L)      // 4096
#define CH    32
#define CLEN  (L/CH)        // 32

typedef unsigned long long ull;

// ---------------- device scratch ----------------
__device__ float g_a1[ROWS*DM];          // inter-layer activation
__device__ float g_xz[ROWS*2*DI];        // in_proj output (xc | z)
__device__ float g_xc[ROWS*DI];          // conv+silu output
__device__ float g_dblp[2][ROWS*48];     // x_proj partial outputs (k-split)
__device__ float g_dt[ROWS*DI];          // softplus dt
__device__ float g_y[ROWS*DI];           // gated scan output
__device__ float g_P[NSEQ*DI*CH*DS];     // per-chunk decay
__device__ float g_H[NSEQ*DI*CH*DS];     // per-chunk end state -> init state

// ---------------- helpers ----------------
__device__ __forceinline__ ull pk2(float x, float y){
    ull r; asm("mov.b64 %0, {%1, %2};" : "=l"(r) : "f"(x), "f"(y)); return r;
}
__device__ __forceinline__ float2 upk2(ull v){
    float2 f; asm("mov.b64 {%0, %1}, %2;" : "=f"(f.x), "=f"(f.y) : "l"(v)); return f;
}
__device__ __forceinline__ void ffma2(ull &c, ull a, ull b){
    asm("fma.rn.f32x2 %0, %1, %2, %0;" : "+l"(c) : "l"(a), "l"(b));
}
__device__ __forceinline__ float ex2f(float x){
    float r; asm("ex2.approx.ftz.f32 %0, %1;" : "=f"(r) : "f"(x)); return r;
}
#define LOG2E 1.4426950408889634f
__device__ __forceinline__ float silu_f(float x){ return x / (1.f + ex2f(-LOG2E*x)); }
__device__ __forceinline__ float softplus_f(float x){ return x > 20.f ? x : log1pf(expf(x)); }

// row remap helpers (prep / final fused into GEMM)
__device__ __forceinline__ const float* arow(const float* Abase, int asel, int rr, int K,
                                             const float* xp){
    if (asel == 3){
        int sio = rr>>10, b = sio&1, c = sio>>1, l = rr&(L-1);
        return xp + ((size_t)(b*L + (c ? (L-1-l) : l)))*DM;
    }
    return Abase + (size_t)rr*K;
}
__device__ __forceinline__ float* crow(float* Cbase, int csel, int rr, int N, float* outp){
    if (csel == 3){
        int sio = rr>>10, b = sio&1, c = sio>>1, l = rr&(L-1);
        return outp + ((size_t)(b*L + (c ? (L-1-l) : l)))*(2*DM) + c*DM;
    }
    return Cbase + (size_t)rr*N;
}

// ============== gemm2: C[r,n] = sum_k A[r,k]*W[n,k] ==============
template<int BM, int BN>
__global__ __launch_bounds__(256) void gemm2(int asel, const float* __restrict__ Wall,
                                             int csel, int N, int K, int lay,
                                             const float* __restrict__ xin,
                                             float* __restrict__ outp)
{
    const float* A    = (asel==1) ? g_a1 : g_y;   // asel==3 handled in arow
    float*       Cout = (csel==1) ? g_a1 : g_xz;

    constexpr int RT = BM/16;             // rows per thread
    constexpr int NP = RT/2;              // row pairs per thread
    constexpr int CN = BN/16;             // cols per thread

    __shared__ float As[16*(BM+4)];
    __shared__ float Bs[16*(BN+4)];

    int tid = threadIdx.x;
    int tx  = tid & 15, ty = tid >> 4;
    int r0  = blockIdx.y*BM;
    int n0  = blockIdx.x*BN;
    int si  = r0 >> 10;
    int wl  = lay + 2*(si>>1);
    const float* W = Wall + (size_t)wl*N*K;

    ull acc[NP][CN];
    #pragma unroll
    for (int p=0;p<NP;p++)
        #pragma unroll
        for (int c=0;c<CN;c++) acc[p][c]=0ull;

    int ra = (tid>>2), ka = (tid&3)*4;

    for (int k0=0; k0<K; k0+=16){
        #pragma unroll
        for (int it=0; it<BM/64; it++){
            int r = ra + it*64;
            const float* ap = arow(A, asel, r0+r, K, xin);
            float4 v = *(const float4*)(ap + k0 + ka);
            As[(ka+0)*(BM+4)+r]=v.x; As[(ka+1)*(BM+4)+r]=v.y;
            As[(ka+2)*(BM+4)+r]=v.z; As[(ka+3)*(BM+4)+r]=v.w;
        }
        #pragma unroll
        for (int it=0; it<BN/64; it++){
            int n = ra + it*64;
            float4 v = *(const float4*)(W + (size_t)(n0+n)*K + k0 + ka);
            Bs[(ka+0)*(BN+4)+n]=v.x; Bs[(ka+1)*(BN+4)+n]=v.y;
            Bs[(ka+2)*(BN+4)+n]=v.z; Bs[(ka+3)*(BN+4)+n]=v.w;
        }
        __syncthreads();
        #pragma unroll
        for (int k=0;k<16;k++){
            const ull* ap = (const ull*)&As[k*(BM+4) + ty*RT];
            ull av[NP];
            #pragma unroll
            for (int p=0;p<NP;p++) av[p]=ap[p];
            float bv[CN];
            #pragma unroll
            for (int v4=0; v4<CN/4; v4++){
                float4 b4 = *(const float4*)&Bs[k*(BN+4) + tx*CN + v4*4];
                bv[v4*4+0]=b4.x; bv[v4*4+1]=b4.y; bv[v4*4+2]=b4.z; bv[v4*4+3]=b4.w;
            }
            #pragma unroll
            for (int c=0;c<CN;c++){
                ull bb = pk2(bv[c], bv[c]);
                #pragma unroll
                for (int p=0;p<NP;p++) ffma2(acc[p][c], av[p], bb);
            }
        }
        __syncthreads();
    }
    #pragma unroll
    for (int p=0;p<NP;p++){
        float lo[CN], hi[CN];
        #pragma unroll
        for (int c=0;c<CN;c++){ float2 v = upk2(acc[p][c]); lo[c]=v.x; hi[c]=v.y; }
        float* c0 = crow(Cout, csel, r0 + ty*RT + 2*p,     N, outp) + n0 + tx*CN;
        float* c1 = crow(Cout, csel, r0 + ty*RT + 2*p + 1, N, outp) + n0 + tx*CN;
        #pragma unroll
        for (int v4=0; v4<CN/4; v4++){
            ((float4*)c0)[v4] = make_float4(lo[4*v4],lo[4*v4+1],lo[4*v4+2],lo[4*v4+3]);
            ((float4*)c1)[v4] = make_float4(hi[4*v4],hi[4*v4+1],hi[4*v4+2],hi[4*v4+3]);
        }
    }
}

// ============== xproj3: fused conv+silu + dbl = xc @ Wx^T (k-split x2) ==============
__global__ __launch_bounds__(256) void xproj3(const float* __restrict__ Wx,
                                              const float* __restrict__ cw,
                                              const float* __restrict__ cb, int lay){
    __shared__ float sA[32*130];
    __shared__ float sW[48*130];

    int tid = threadIdx.x;
    int tx  = tid & 15, ty = tid >> 4;
    int r0  = blockIdx.x*32;
    int kh  = blockIdx.y;            // k half: [kh*256, kh*256+256)
    int si  = r0 >> 10;
    int wl  = lay + 2*(si>>1);
    const float* Wb  = Wx + (size_t)wl*48*DI;
    const float* cwb = cw + (size_t)wl*DI*4;
    const float* cbb = cb + (size_t)wl*DI;

    ull acc[2][3];
    #pragma unroll
    for (int i=0;i<2;i++){ acc[i][0]=0ull; acc[i][1]=0ull; acc[i][2]=0ull; }

    for (int kc=0; kc<2; kc++){
        int k0 = kh*256 + kc*128;
        #pragma unroll
        for (int it=0; it<4; it++){
            int i = tid + it*256;            // 0..1023
            int r = i>>5, q = i&31;
            int rr = r0 + r, l = rr & (L-1);
            int d0 = k0 + q*4;
            const float* xp = g_xz + (size_t)rr*(2*DI) + d0;
            float4 z4 = make_float4(0.f,0.f,0.f,0.f);
            float4 v0 = (l>=3) ? *(const float4*)(xp - 3*(2*DI)) : z4;
            float4 v1 = (l>=2) ? *(const float4*)(xp - 2*(2*DI)) : z4;
            float4 v2 = (l>=1) ? *(const float4*)(xp - 1*(2*DI)) : z4;
            float4 v3 = *(const float4*)(xp);
            float4 w0 = *(const float4*)(cwb + (size_t)d0*4);
            float4 w1 = *(const float4*)(cwb + (size_t)d0*4 + 4);
            float4 w2 = *(const float4*)(cwb + (size_t)d0*4 + 8);
            float4 w3 = *(const float4*)(cwb + (size_t)d0*4 + 12);
            float4 bb = *(const float4*)(cbb + d0);
            float s0 = bb.x + v0.x*w0.x + v1.x*w0.y + v2.x*w0.z + v3.x*w0.w;
            float s1 = bb.y + v0.y*w1.x + v1.y*w1.y + v2.y*w1.z + v3.y*w1.w;
            float s2 = bb.z + v0.z*w2.x + v1.z*w2.y + v2.z*w2.z + v3.z*w2.w;
            float s3 = bb.w + v0.w*w3.x + v1.w*w3.y + v2.w*w3.z + v3.w*w3.w;
            s0 = silu_f(s0); s1 = silu_f(s1); s2 = silu_f(s2); s3 = silu_f(s3);
            float* ap = &sA[r*130 + q*4];
            ap[0]=s0; ap[1]=s1; ap[2]=s2; ap[3]=s3;
            *(float4*)(g_xc + (size_t)rr*DI + d0) = make_float4(s0,s1,s2,s3);
        }
        #pragma unroll
        for (int it=0; it<6; it++){
            int i = tid + it*256;            // 0..1535
            int j = i>>5, q = i&31;
            float4 v = *(const float4*)(Wb + (size_t)j*DI + k0 + q*4);
            float* wp = &sW[j*130 + q*4];
            wp[0]=v.x; wp[1]=v.y; wp[2]=v.z; wp[3]=v.w;
        }
        __syncthreads();
        const ull* a0p = (const ull*)&sA[(ty*2  )*130];
        const ull* a1p = (const ull*)&sA[(ty*2+1)*130];
        const ull* w0p = (const ull*)&sW[(tx    )*130];
        const ull* w1p = (const ull*)&sW[(tx+16 )*130];
        const ull* w2p = (const ull*)&sW[(tx+32 )*130];
        #pragma unroll 8
        for (int k2=0;k2<64;k2++){
            ull a0=a0p[k2], a1=a1p[k2];
            ull b0=w0p[k2], b1=w1p[k2], b2=w2p[k2];
            ffma2(acc[0][0],a0,b0); ffma2(acc[0][1],a0,b1); ffma2(acc[0][2],a0,b2);
            ffma2(acc[1][0],a1,b0); ffma2(acc[1][1],a1,b1); ffma2(acc[1][2],a1,b2);
        }
        __syncthreads();
    }
    #pragma unroll
    for (int i=0;i<2;i++){
        int rr = r0 + ty*2 + i;
        float* dp = g_dblp[kh] + (size_t)rr*48;
        float2 v0=upk2(acc[i][0]), v1=upk2(acc[i][1]), v2=upk2(acc[i][2]);
        dp[tx]    = v0.x+v0.y;
        dp[tx+16] = v1.x+v1.y;
        dp[tx+32] = v2.x+v2.y;
    }
}

// ---------------- dt = softplus((p0+p1)[0:16] @ Wdt^T + b) ----------------
__global__ void dt_kernel(const float* __restrict__ Wdt, const float* __restrict__ bdt, int lay){
    int idx = blockIdx.x*blockDim.x + threadIdx.x;   // ROWS*DI
    int d  = idx & (DI-1);
    int r  = idx >> 9;
    int si = r >> 10;
    int wl = lay + 2*(si>>1);
    const float4* d0 = (const float4*)(g_dblp[0] + (size_t)r*48);
    const float4* d1 = (const float4*)(g_dblp[1] + (size_t)r*48);
    const float4* w  = (const float4*)(Wdt + (size_t)(wl*DI + d)*RK);
    float acc = bdt[wl*DI + d];
    #pragma unroll
    for (int q=0;q<RK/4;q++){
        float4 a = d0[q], a2 = d1[q], b = w[q];
        acc += (a.x+a2.x)*b.x + (a.y+a2.y)*b.y + (a.z+a2.z)*b.z + (a.w+a2.w)*b.w;
    }
    g_dt[idx] = softplus_f(acc);
}

// ---------------- scan phase 1: chunk-local end state + chunk decay ----------------
// All chunk inputs staged in smem via coalesced float4 loads; inner loop LDS/MUFU/FMA only.
__global__ __launch_bounds__(128) void scan_phase1(const float* __restrict__ A_log, int lay){
    int tid = threadIdx.x;
    int d0b = blockIdx.x*128;                // d block base
    int d   = d0b + tid;
    int ch  = blockIdx.y;                    // 32
    int si  = blockIdx.z;                    // 4
    int wl  = lay + 2*(si>>1);
    __shared__ float sdt[CLEN][128];
    __shared__ float sxc[CLEN][128];
    __shared__ float sB[CLEN][DS];
    int rbase = si*L + ch*CLEN;
    // dt/xc tiles: CLEN*128 floats = 1024 float4, 8 per thread, coalesced
    #pragma unroll
    for (int it=0; it<8; it++){
        int i  = tid + it*128;               // float4 index
        int ll = i >> 5, dd = (i & 31)*4;
        *(float4*)&sdt[ll][dd] = *(const float4*)(g_dt + (size_t)(rbase+ll)*DI + d0b + dd);
        *(float4*)&sxc[ll][dd] = *(const float4*)(g_xc + (size_t)(rbase+ll)*DI + d0b + dd);
    }
    for (int i=tid; i<CLEN*DS; i+=128){
        int ll = i>>4, s = i&15;
        size_t off = (size_t)(rbase+ll)*48 + 16 + s;
        sB[ll][s] = g_dblp[0][off] + g_dblp[1][off];
    }
    __syncthreads();
    float A2[DS], h[DS];
    #pragma unroll
    for (int s=0;s<DS;s++){
        A2[s] = -expf(A_log[(size_t)(wl*DI+d)*DS + s]) * LOG2E;
        h[s]=0.f;
    }
    float sdtacc = 0.f;
    #pragma unroll 4
    for (int ll=0; ll<CLEN; ll++){
        float dtc = sdt[ll][tid];
        float xcv = sxc[ll][tid];
        float dtx = dtc*xcv;
        sdtacc += dtc;
        #pragma unroll
        for (int s=0;s<DS;s++){
            float dA = ex2f(dtc*A2[s]);
            h[s] = fmaf(dA, h[s], dtx*sB[ll][s]);
        }
    }
    size_t ob = ((size_t)(si*DI + d)*CH + ch)*DS;
    #pragma unroll
    for (int s=0;s<DS;s++){
        g_H[ob+s] = h[s];
        g_P[ob+s] = ex2f(sdtacc*A2[s]);
    }
}

// ---------------- scan combine: serial scan of CH chunk aggregates ----------------
__global__ void scan_comb(){
    int idx = blockIdx.x*blockDim.x + threadIdx.x;   // NSEQ*DI*DS = 32768
    int s = idx & 15;
    int t = idx >> 4;
    size_t base = (size_t)t*CH*DS + s;
    float run = 0.f;
    #pragma unroll
    for (int c=0;c<CH;c++){
        size_t p = base + (size_t)c*DS;
        float he = g_H[p], pe = g_P[p];
        g_H[p] = run;
        run = fmaf(pe, run, he);
    }
}

// ---------------- scan phase 2: replay with true init, + xc*D, * silu(z) ----------------
__global__ __launch_bounds__(128) void scan_phase2(const float* __restrict__ A_log,
                                                   const float* __restrict__ Dp, int lay){
    int tid = threadIdx.x;
    int d0b = blockIdx.x*128;
    int d   = d0b + tid;
    int ch  = blockIdx.y;
    int si  = blockIdx.z;
    int wl  = lay + 2*(si>>1);
    __shared__ float sdt[CLEN][128];
    __shared__ float sxc[CLEN][128];
    __shared__ float sB[CLEN][DS];
    __shared__ float sC[CLEN][DS];
    int rbase = si*L + ch*CLEN;
    #pragma unroll
    for (int it=0; it<8; it++){
        int i  = tid + it*128;
        int ll = i >> 5, dd = (i & 31)*4;
        *(float4*)&sdt[ll][dd] = *(const float4*)(g_dt + (size_t)(rbase+ll)*DI + d0b + dd);
        *(float4*)&sxc[ll][dd] = *(const float4*)(g_xc + (size_t)(rbase+ll)*DI + d0b + dd);
    }
    for (int i=tid; i<CLEN*DS; i+=128){
        int ll = i>>4, s = i&15;
        size_t off = (size_t)(rbase+ll)*48 + 16 + s;
        sB[ll][s] = g_dblp[0][off]    + g_dblp[1][off];
        sC[ll][s] = g_dblp[0][off+16] + g_dblp[1][off+16];
    }
    __syncthreads();
    float A2[DS], h[DS];
    size_t ib = ((size_t)(si*DI + d)*CH + ch)*DS;
    #pragma unroll
    for (int s=0;s<DS;s++){
        A2[s] = -expf(A_log[(size_t)(wl*DI+d)*DS + s]) * LOG2E;
        h[s]  = g_H[ib+s];
    }
    float Dd = Dp[wl*DI + d];
    #pragma unroll 4
    for (int ll=0; ll<CLEN; ll++){
        int r = rbase + ll;
        float dtc = sdt[ll][tid];
        float xcv = sxc[ll][tid];
        float z   = g_xz[(size_t)r*(2*DI) + DI + d];
        float dtx = dtc*xcv;
        #pragma unroll
        for (int s=0;s<DS;s++){
            float dA = ex2f(dtc*A2[s]);
            h[s] = fmaf(dA, h[s], dtx*sB[ll][s]);
        }
        float y0=0.f,y1=0.f,y2=0.f,y3=0.f;
        #pragma unroll
        for (int s=0;s<DS;s+=4){
            y0 = fmaf(h[s+0], sC[ll][s+0], y0);
            y1 = fmaf(h[s+1], sC[ll][s+1], y1);
            y2 = fmaf(h[s+2], sC[ll][s+2], y2);
            y3 = fmaf(h[s+3], sC[ll][s+3], y3);
        }
        float y = (y0+y1)+(y2+y3);
        y = fmaf(xcv, Dd, y);
        y *= silu_f(z);
        g_y[(size_t)r*DI + d] = y;
    }
}

// ---------------- launch ----------------
extern "C" void kernel_launch(void* const* d_in, const int* in_sizes, int n_in,
                              void* d_out, int out_size)
{
    (void)in_sizes; (void)n_in; (void)out_size;
    const float* x        = (const float*)d_in[0];
    const float* in_proj  = (const float*)d_in[1];
    const float* conv_w   = (const float*)d_in[2];
    const float* conv_b   = (const float*)d_in[3];
    const float* x_proj   = (const float*)d_in[4];
    const float* dt_proj  = (const float*)d_in[5];
    const float* dt_bias  = (const float*)d_in[6];
    const float* A_log    = (const float*)d_in[7];
    const float* Dp       = (const float*)d_in[8];
    const float* out_proj = (const float*)d_in[9];
    float* out = (float*)d_out;

    for (int lay = 0; lay < 2; lay++){
        int ain  = lay ? 1 : 3;        // layer0 reads x with prep-remap, layer1 reads g_a1
        int cout = lay ? 3 : 1;        // layer1 writes out with final-remap, layer0 -> g_a1

        gemm2<128,128><<<dim3((2*DI)/128, ROWS/128), 256>>>(ain, in_proj, 2, 2*DI, DM, lay, x, nullptr);
        xproj3<<<dim3(ROWS/32, 2), 256>>>(x_proj, conv_w, conv_b, lay);
        dt_kernel<<<ROWS*DI/256, 256>>>(dt_proj, dt_bias, lay);
        scan_phase1<<<dim3(DI/128, CH, NSEQ), 128>>>(A_log, lay);
        scan_comb<<<NSEQ*DI*DS/256, 256>>>();
        scan_phase2<<<dim3(DI/128, CH, NSEQ), 128>>>(A_log, Dp, lay);
        gemm2<64,64><<<dim3(DM/64, ROWS/64), 256>>>(2, out_proj, cout, DM, DI, lay, nullptr, out);
    }
}